// round 16
// baseline (speedup 1.0000x reference)
#include <cuda_runtime.h>
#include <math.h>

#define LRELU(v) ((v) >= 0.0f ? (v) : 0.01f * (v))

constexpr int B  = 64;
constexpr int C0 = 3;
constexpr int NN = 500;
constexpr int T  = 50;
constexpr int R  = 4;
constexpr int P  = 500;
constexpr int H  = 128;
constexpr int CM = 3;
constexpr int CF = 20;
constexpr int F  = 43;         // 2*CF + C0
constexpr int E_MAX = 16000;
constexpr int BF = B * F;      // 2752
constexpr int BF4 = BF / 4;    // 688

// ---------------- scratch (static device globals; no allocation) ----------------
__device__ float d_x[B * NN * F];            // temporal features, [b][n][f]
__device__ float d_h2[NN * R * B * F];       // transformed feats [src][r][b][f]
__device__ float d_g[B * NN * F];            // gnn root-out, then final gnn feats
__device__ int   d_csr_off[NN + 1];
__device__ int   d_csr_se[E_MAX];            // packed (src<<2)|type, grouped by dst
__device__ float d_invdeg[R * NN];
__device__ float d_gsc[F], d_gsh[F];         // gnn BN scale/shift

// =================================================================================
// Kernel 1: fused temporal features (2048 blocks) + CSR graph build (block 0).
// (Exact version measured at 58us in R12 — scalar conv2, KSP=145/KMP=91.)
// =================================================================================
constexpr int NT  = 16;
constexpr int KS  = CM * 48;   // 144
constexpr int KSP = 145;
constexpr int KM  = CM * 30;   // 90
constexpr int KMP = 91;

struct TemporalSmem {
    float sw2s[CF * KSP];
    float sw2m[CF * KMP];
    float sw1s[CM * C0 * 3];
    float sw1m[CM * C0 * 21];
    float sobs[C0][NT][T];
    float sacts[NT * KSP];
    float sactm[NT * KMP];
    float a1s[CM], c1s[CM], a1m[CM], c1m[CM];
    float a2s[CF], c2s[CF], a2m[CF], c2m[CF];
};
struct GraphSmem {
    int cnt_all[NN];
    int cnt_rt[R * NN];
    int off[NN + 1];
    int cur[NN];
};
union SmemU {
    TemporalSmem t;
    GraphSmem g;
};

__global__ __launch_bounds__(256) void k_temporal(
    const float* __restrict__ obs,
    const int* __restrict__ ei, const int* __restrict__ et, int E,
    const float* __restrict__ gbn,
    const float* __restrict__ sc1_w, const float* __restrict__ sc1_b, const float* __restrict__ sbn1,
    const float* __restrict__ sc2_w, const float* __restrict__ sc2_b, const float* __restrict__ sbn2,
    const float* __restrict__ mc1_w, const float* __restrict__ mc1_b, const float* __restrict__ mbn1,
    const float* __restrict__ mc2_w, const float* __restrict__ mc2_b, const float* __restrict__ mbn2)
{
    __shared__ SmemU sm;
    const int tid = threadIdx.x;

    // ---------------- block 0: CSR graph build (hidden under conv blocks) ----
    if (blockIdx.x == 0) {
        for (int i = tid; i < NN; i += 256) sm.g.cnt_all[i] = 0;
        for (int i = tid; i < R * NN; i += 256) sm.g.cnt_rt[i] = 0;
        __syncthreads();
        for (int e = tid; e < E; e += 256) {
            int d = ei[E + e];
            atomicAdd(&sm.g.cnt_all[d], 1);
            atomicAdd(&sm.g.cnt_rt[et[e] * NN + d], 1);
        }
        __syncthreads();
        if (tid < 32) {
            int carry = 0;
            for (int base = 0; base < NN; base += 32) {
                int idx = base + tid;
                int c = (idx < NN) ? sm.g.cnt_all[idx] : 0;
                int v = c;
                #pragma unroll
                for (int o = 1; o < 32; o <<= 1) {
                    int t2 = __shfl_up_sync(0xffffffffu, v, o);
                    if (tid >= o) v += t2;
                }
                if (idx < NN) sm.g.off[idx] = carry + v - c;
                carry += __shfl_sync(0xffffffffu, v, 31);
            }
            if (tid == 0) sm.g.off[NN] = carry;
        }
        __syncthreads();
        for (int i = tid; i <= NN; i += 256) d_csr_off[i] = sm.g.off[i];
        for (int i = tid; i < NN; i += 256) sm.g.cur[i] = sm.g.off[i];
        for (int i = tid; i < R * NN; i += 256) {
            int c = sm.g.cnt_rt[i];
            d_invdeg[i] = 1.0f / (float)(c > 1 ? c : 1);
        }
        if (tid < F) {
            float g = gbn[tid], be = gbn[F + tid], mu = gbn[2 * F + tid], vv = gbn[3 * F + tid];
            float sc = g * rsqrtf(vv + 1e-5f);
            d_gsc[tid] = sc;
            d_gsh[tid] = be - mu * sc;
        }
        __syncthreads();
        for (int e = tid; e < E; e += 256) {
            int d = ei[E + e];
            int p = atomicAdd(&sm.g.cur[d], 1);
            d_csr_se[p] = (ei[e] << 2) | et[e];
        }
        return;
    }

    // ---------------- temporal path ----------------
    const int bid = blockIdx.x - 1;
    const int b  = bid >> 5;
    const int n0 = (bid & 31) * NT;

    for (int i = tid; i < CF * KS; i += 256) sm.t.sw2s[(i / KS) * KSP + (i % KS)] = sc2_w[i];
    for (int i = tid; i < CF * KM; i += 256) sm.t.sw2m[(i / KM) * KMP + (i % KM)] = mc2_w[i];
    for (int i = tid; i < CM * C0 * 3;  i += 256) sm.t.sw1s[i] = sc1_w[i];
    for (int i = tid; i < CM * C0 * 21; i += 256) sm.t.sw1m[i] = mc1_w[i];

    if (tid < CM) {
        float g = sbn1[tid], be = sbn1[3 + tid], mu = sbn1[6 + tid], vv = sbn1[9 + tid];
        float sc = g * rsqrtf(vv + 1e-5f);
        sm.t.a1s[tid] = sc; sm.t.c1s[tid] = (be - mu * sc) + sc1_b[tid] * sc;
        g = mbn1[tid]; be = mbn1[3 + tid]; mu = mbn1[6 + tid]; vv = mbn1[9 + tid];
        sc = g * rsqrtf(vv + 1e-5f);
        sm.t.a1m[tid] = sc; sm.t.c1m[tid] = (be - mu * sc) + mc1_b[tid] * sc;
    }
    if (tid < CF) {
        float g = sbn2[tid], be = sbn2[20 + tid], mu = sbn2[40 + tid], vv = sbn2[60 + tid];
        float sc = g * rsqrtf(vv + 1e-5f);
        sm.t.a2s[tid] = sc; sm.t.c2s[tid] = (be - mu * sc) + sc2_b[tid] * sc;
        g = mbn2[tid]; be = mbn2[20 + tid]; mu = mbn2[40 + tid]; vv = mbn2[60 + tid];
        sc = g * rsqrtf(vv + 1e-5f);
        sm.t.a2m[tid] = sc; sm.t.c2m[tid] = (be - mu * sc) + mc2_b[tid] * sc;
    }

    for (int i = tid; i < C0 * NT * T; i += 256) {
        int c = i / (NT * T);
        int rem = i % (NT * T);
        int ni = rem / T, t = rem % T;
        int n = n0 + ni;
        sm.t.sobs[c][ni][t] = (n < NN) ? obs[((b * C0 + c) * NN + n) * T + t] : 0.0f;
    }
    __syncthreads();

    // conv1 s-branch: 192 tasks (ni, c, 12-wide j block), register sliding window
    if (tid < 192) {
        int ni = tid / 12;
        int rem = tid % 12;
        int c = rem / 4, jb = rem % 4;
        int j0 = jb * 12;
        float acc[12];
        #pragma unroll
        for (int j = 0; j < 12; j++) acc[j] = 0.0f;
        #pragma unroll
        for (int ci = 0; ci < C0; ci++) {
            float win[14];
            #pragma unroll
            for (int t2 = 0; t2 < 14; t2++) win[t2] = sm.t.sobs[ci][ni][j0 + t2];
            #pragma unroll
            for (int k = 0; k < 3; k++) {
                float wv = sm.t.sw1s[c * 9 + ci * 3 + k];
                #pragma unroll
                for (int j = 0; j < 12; j++) acc[j] += win[j + k] * wv;
            }
        }
        float aa = sm.t.a1s[c], cc = sm.t.c1s[c];
        #pragma unroll
        for (int j = 0; j < 12; j++) {
            float v = acc[j] * aa + cc;
            sm.t.sacts[ni * KSP + c * 48 + j0 + j] = LRELU(v);
        }
    }
    // conv1 m-branch: 144 tasks (ni, c, 10-wide j block)
    if (tid < 144) {
        int ni = tid / 9;
        int rem = tid % 9;
        int c = rem / 3, jb = rem % 3;
        int j0 = jb * 10;
        float acc[10];
        #pragma unroll
        for (int j = 0; j < 10; j++) acc[j] = 0.0f;
        #pragma unroll
        for (int ci = 0; ci < C0; ci++) {
            float win[30];
            #pragma unroll
            for (int t2 = 0; t2 < 30; t2++) win[t2] = sm.t.sobs[ci][ni][j0 + t2];
            #pragma unroll
            for (int k = 0; k < 21; k++) {
                float wv = sm.t.sw1m[c * 63 + ci * 21 + k];
                #pragma unroll
                for (int j = 0; j < 10; j++) acc[j] += win[j + k] * wv;
            }
        }
        float aa = sm.t.a1m[c], cc = sm.t.c1m[c];
        #pragma unroll
        for (int j = 0; j < 10; j++) {
            float v = acc[j] * aa + cc;
            sm.t.sactm[ni * KMP + c * 30 + j0 + j] = LRELU(v);
        }
    }
    __syncthreads();

    // conv2: 2ni x 2cf register tiles, l-branch tasks 160..207
    if (tid < 80) {
        int nip = tid / 10, cfp = tid % 10;
        int ni0 = nip * 2, cf0 = cfp * 2;
        const float* a0 = &sm.t.sacts[ni0 * KSP];
        const float* a1 = &sm.t.sacts[(ni0 + 1) * KSP];
        const float* w0 = &sm.t.sw2s[cf0 * KSP];
        const float* w1 = &sm.t.sw2s[(cf0 + 1) * KSP];
        float acc00 = 0.f, acc01 = 0.f, acc10 = 0.f, acc11 = 0.f;
        #pragma unroll 8
        for (int k = 0; k < KS; k++) {
            float av0 = a0[k], av1 = a1[k];
            float wv0 = w0[k], wv1 = w1[k];
            acc00 += av0 * wv0; acc01 += av0 * wv1;
            acc10 += av1 * wv0; acc11 += av1 * wv1;
        }
        #pragma unroll
        for (int di = 0; di < 2; di++) {
            int n = n0 + ni0 + di;
            if (n >= NN) continue;
            float va = (di == 0) ? acc00 : acc10;
            float vb = (di == 0) ? acc01 : acc11;
            va = va * sm.t.a2s[cf0] + sm.t.c2s[cf0];
            vb = vb * sm.t.a2s[cf0 + 1] + sm.t.c2s[cf0 + 1];
            d_x[(size_t)(b * NN + n) * F + cf0]     = LRELU(va);
            d_x[(size_t)(b * NN + n) * F + cf0 + 1] = LRELU(vb);
        }
    } else if (tid < 160) {
        int t2 = tid - 80;
        int nip = t2 / 10, cfp = t2 % 10;
        int ni0 = nip * 2, cf0 = cfp * 2;
        const float* a0 = &sm.t.sactm[ni0 * KMP];
        const float* a1 = &sm.t.sactm[(ni0 + 1) * KMP];
        const float* w0 = &sm.t.sw2m[cf0 * KMP];
        const float* w1 = &sm.t.sw2m[(cf0 + 1) * KMP];
        float acc00 = 0.f, acc01 = 0.f, acc10 = 0.f, acc11 = 0.f;
        #pragma unroll 6
        for (int k = 0; k < KM; k++) {
            float av0 = a0[k], av1 = a1[k];
            float wv0 = w0[k], wv1 = w1[k];
            acc00 += av0 * wv0; acc01 += av0 * wv1;
            acc10 += av1 * wv0; acc11 += av1 * wv1;
        }
        #pragma unroll
        for (int di = 0; di < 2; di++) {
            int n = n0 + ni0 + di;
            if (n >= NN) continue;
            float va = (di == 0) ? acc00 : acc10;
            float vb = (di == 0) ? acc01 : acc11;
            va = va * sm.t.a2m[cf0] + sm.t.c2m[cf0];
            vb = vb * sm.t.a2m[cf0 + 1] + sm.t.c2m[cf0 + 1];
            d_x[(size_t)(b * NN + n) * F + 20 + cf0]     = LRELU(va);
            d_x[(size_t)(b * NN + n) * F + 20 + cf0 + 1] = LRELU(vb);
        }
    } else if (tid < 208) {
        int i2 = tid - 160;
        int ni = i2 / C0, c = i2 % C0;
        int n = n0 + ni;
        float mx = sm.t.sobs[c][ni][0];
        #pragma unroll
        for (int t = 1; t < T; t++) mx = fmaxf(mx, sm.t.sobs[c][ni][t]);
        if (n < NN) d_x[(size_t)(b * NN + n) * F + 40 + c] = LRELU(mx);
    }
}

// =================================================================================
// Kernel 2: y = x @ [gw_root | gw_rel0..3]  (32000 x 43) @ (43 x 215)
// =================================================================================
__global__ __launch_bounds__(256) void k_gnn_mm(
    const float* __restrict__ gw_root, const float* __restrict__ gw_rel,
    const float* __restrict__ g_b)
{
    __shared__ float xs[F * 65];
    __shared__ float sW[F * 216];
    __shared__ float sgb[F];

    const int tid = threadIdx.x;
    const int r0 = blockIdx.x * 64;

    for (int i = tid; i < 64 * F; i += 256) {
        int rr = i / F, k = i % F;
        xs[k * 65 + rr] = d_x[(size_t)(r0 + rr) * F + k];
    }
    for (int i = tid; i < F * 215; i += 256) {
        int k = i / 215, col = i % 215;
        float v;
        if (col < F) v = gw_root[k * F + col];
        else {
            int cc = col - F;
            int rr = cc / F, g = cc % F;
            v = gw_rel[(rr * F + k) * F + g];
        }
        sW[k * 216 + col] = v;
    }
    if (tid < F) sgb[tid] = g_b[tid];
    __syncthreads();

    if (tid < 216) {
        int rg = tid % 8;
        int cc = tid / 8;
        int col0 = cc * 8;
        float acc[8][8];
        #pragma unroll
        for (int i = 0; i < 8; i++)
            #pragma unroll
            for (int j = 0; j < 8; j++) acc[i][j] = 0.0f;

        for (int k = 0; k < F; k++) {
            float xv[8], wv[8];
            #pragma unroll
            for (int i = 0; i < 8; i++) xv[i] = xs[k * 65 + rg * 8 + i];
            #pragma unroll
            for (int j = 0; j < 8; j++) wv[j] = sW[k * 216 + col0 + j];
            #pragma unroll
            for (int i = 0; i < 8; i++)
                #pragma unroll
                for (int j = 0; j < 8; j++) acc[i][j] += xv[i] * wv[j];
        }
        #pragma unroll
        for (int i = 0; i < 8; i++) {
            int row = r0 + rg * 8 + i;
            int bb = row / NN, n = row % NN;
            #pragma unroll
            for (int j = 0; j < 8; j++) {
                int col = col0 + j;
                if (col < 215) {
                    if (col < F) {
                        d_g[(size_t)row * F + col] = acc[i][j] + sgb[col];
                    } else {
                        int cc2 = col - F;
                        int rr = cc2 / F, g = cc2 % F;
                        d_h2[(size_t)((n * R + rr) * B + bb) * F + g] = acc[i][j];
                    }
                }
            }
        }
    }
}

// =================================================================================
// Kernel 3: message aggregation. Two blocks per dst node (simple R9 version,
// regs=40, measured 34.5us — batching was neutral and costs occupancy).
// =================================================================================
__global__ __launch_bounds__(256) void k_agg()
{
    constexpr int CH = 128;
    constexpr int HALF4 = BF4 / 2;        // 344 float4 per half
    __shared__ int   sbase[CH];
    __shared__ float sws[CH];

    const int tid = threadIdx.x;
    const int n = blockIdx.x >> 1;
    const int s = blockIdx.x & 1;
    const int j4base = s * HALF4;
    const int off0 = d_csr_off[n];
    const int cnt  = d_csr_off[n + 1] - off0;

    float4 acc0 = make_float4(0.f, 0.f, 0.f, 0.f);
    float4 acc1 = make_float4(0.f, 0.f, 0.f, 0.f);

    for (int base = 0; base < cnt; base += CH) {
        int lim = min(CH, cnt - base);
        if (tid < lim) {
            int se = d_csr_se[off0 + base + tid];
            int src = se >> 2, r = se & 3;
            sbase[tid] = (src * R + r) * BF;
            sws[tid]   = d_invdeg[r * NN + n];
        }
        __syncthreads();
        for (int i = 0; i < lim; i++) {
            const float4* hp = (const float4*)(d_h2 + sbase[i]) + j4base;
            const float w = sws[i];
            float4 v0 = hp[tid];
            acc0.x += v0.x * w; acc0.y += v0.y * w; acc0.z += v0.z * w; acc0.w += v0.w * w;
            if (tid < HALF4 - 256) {
                float4 v1 = hp[tid + 256];
                acc1.x += v1.x * w; acc1.y += v1.y * w; acc1.z += v1.z * w; acc1.w += v1.w * w;
            }
        }
        __syncthreads();
    }

    float accs[8] = {acc0.x, acc0.y, acc0.z, acc0.w,
                     acc1.x, acc1.y, acc1.z, acc1.w};
    #pragma unroll
    for (int u = 0; u < 2; u++) {
        int j4 = j4base + tid + 256 * u;
        if (tid + 256 * u < HALF4) {
            #pragma unroll
            for (int c = 0; c < 4; c++) {
                int j = j4 * 4 + c;
                int bb = j / F, f = j % F;
                size_t idx = (size_t)(bb * NN + n) * F + f;
                float v = d_g[idx] + accs[u * 4 + c];
                v = v * d_gsc[f] + d_gsh[f];
                d_g[idx] = LRELU(v);
            }
        }
    }
}

// =================================================================================
// Kernel 4: head = coalesced logits (warp-per-p) + MLP + softmax, one block per b.
// Merging avoids the 11us standalone logits kernel + its launch + d_o round-trip.
// =================================================================================
__global__ __launch_bounds__(512) void k_head(
    const float* __restrict__ action, const int* __restrict__ nsel,
    const float* __restrict__ a_cw, const float* __restrict__ a_cb,
    const float* __restrict__ w1, const float* __restrict__ b1,
    const float* __restrict__ w2, const float* __restrict__ b2,
    const float* __restrict__ w3, const float* __restrict__ b3,
    float* __restrict__ out)
{
    __shared__ float so[P + 1];
    __shared__ float sh1[H];
    __shared__ float sh2[H];
    __shared__ float sz[P + 1];
    __shared__ float sacw[88];
    __shared__ float sred[512];

    const int tid = threadIdx.x;
    const int b = blockIdx.x;
    const int wid = tid >> 5;
    const int lane = tid & 31;
    const int quarter = tid >> 7;       // 0..3
    const int o = tid & 127;

    if (tid < 87) sacw[tid] = a_cw[tid];
    if (tid == 87) sacw[87] = a_cb[0];
    if (tid == 0) so[0] = 0.0f;
    __syncthreads();

    // ---- logits: warp per p, coalesced row loads + shuffle reduce ----
    for (int p = wid; p < P; p += 16) {
        int node = nsel[p];
        const float* xr = d_x + (size_t)(b * NN + node) * F;
        const float* gr = d_g + (size_t)(b * NN + node) * F;
        float acc = sacw[1 + lane] * xr[lane] + sacw[44 + lane] * gr[lane];
        if (lane < F - 32)
            acc += sacw[33 + lane] * xr[lane + 32] + sacw[76 + lane] * gr[lane + 32];
        if (lane == 0)
            acc += sacw[87] + sacw[0] * action[b * (P + 1) + p + 1];
        #pragma unroll
        for (int off = 16; off > 0; off >>= 1)
            acc += __shfl_down_sync(0xffffffffu, acc, off);
        if (lane == 0) so[p + 1] = acc;
    }
    __syncthreads();

    // ---- h1: k = 501 split 4 ways ----
    {
        const int k0 = quarter * 126;
        const int k1 = min(501, k0 + 126);
        float acc = (quarter == 0) ? b1[o] : 0.0f;
        #pragma unroll 6
        for (int k = k0; k < k1; k++) acc += so[k] * w1[k * H + o];
        sred[tid] = acc;
        __syncthreads();
        if (tid < H)
            sh1[tid] = fmaxf(sred[tid] + sred[tid + 128] + sred[tid + 256] + sred[tid + 384], 0.0f);
        __syncthreads();
    }

    // ---- h2: k = 128 split 4 ways ----
    {
        const int k0 = quarter * 32;
        float acc = (quarter == 0) ? b2[o] : 0.0f;
        #pragma unroll 8
        for (int k = k0; k < k0 + 32; k++) acc += sh1[k] * w2[k * H + o];
        sred[tid] = acc;
        __syncthreads();
        if (tid < H)
            sh2[tid] = fmaxf(sred[tid] + sred[tid + 128] + sred[tid + 256] + sred[tid + 384], 0.0f);
        __syncthreads();
    }

    // ---- z: one p per thread, k = 128 ----
    if (tid < P + 1) {
        float acc = b3[tid];
        #pragma unroll 16
        for (int k = 0; k < H; k++) acc += sh2[k] * w3[k * (P + 1) + tid];
        sz[tid] = acc;
    }
    __syncthreads();

    // ---- softmax ----
    float lm = (tid < P + 1) ? sz[tid] : -1e30f;
    sred[tid] = lm;
    __syncthreads();
    for (int s = 256; s > 0; s >>= 1) {
        if (tid < s) sred[tid] = fmaxf(sred[tid], sred[tid + s]);
        __syncthreads();
    }
    float mx = sred[0];
    __syncthreads();

    float ls = 0.0f;
    if (tid < P + 1) {
        float e = expf(sz[tid] - mx);
        sz[tid] = e;
        ls = e;
    }
    sred[tid] = ls;
    __syncthreads();
    for (int s = 256; s > 0; s >>= 1) {
        if (tid < s) sred[tid] += sred[tid + s];
        __syncthreads();
    }
    float inv = 1.0f / sred[0];
    if (tid < P + 1)
        out[b * (P + 1) + tid] = sz[tid] * inv;
}

// =================================================================================
extern "C" void kernel_launch(void* const* d_in, const int* in_sizes, int n_in,
                              void* d_out, int out_size)
{
    const float* obs    = (const float*)d_in[0];
    const float* action = (const float*)d_in[1];
    const int*   ei     = (const int*)d_in[2];
    const int*   et     = (const int*)d_in[3];
    const int*   nsel   = (const int*)d_in[4];
    const float* sc1_w  = (const float*)d_in[5];
    const float* sc1_b  = (const float*)d_in[6];
    const float* sbn1   = (const float*)d_in[7];
    const float* sc2_w  = (const float*)d_in[8];
    const float* sc2_b  = (const float*)d_in[9];
    const float* sbn2   = (const float*)d_in[10];
    const float* mc1_w  = (const float*)d_in[11];
    const float* mc1_b  = (const float*)d_in[12];
    const float* mbn1   = (const float*)d_in[13];
    const float* mc2_w  = (const float*)d_in[14];
    const float* mc2_b  = (const float*)d_in[15];
    const float* mbn2   = (const float*)d_in[16];
    const float* gw_root= (const float*)d_in[17];
    const float* gw_rel = (const float*)d_in[18];
    const float* g_b    = (const float*)d_in[19];
    const float* gbn    = (const float*)d_in[20];
    const float* a_cw   = (const float*)d_in[21];
    const float* a_cb   = (const float*)d_in[22];
    const float* a_w1   = (const float*)d_in[23];
    const float* a_b1   = (const float*)d_in[24];
    const float* a_w2   = (const float*)d_in[25];
    const float* a_b2   = (const float*)d_in[26];
    const float* a_w3   = (const float*)d_in[27];
    const float* a_b3   = (const float*)d_in[28];

    const int E = in_sizes[3];

    k_temporal<<<B * 32 + 1, 256>>>(obs, ei, et, E, gbn,
        sc1_w, sc1_b, sbn1, sc2_w, sc2_b, sbn2,
        mc1_w, mc1_b, mbn1, mc2_w, mc2_b, mbn2);

    k_gnn_mm<<<(B * NN) / 64, 256>>>(gw_root, gw_rel, g_b);

    k_agg<<<NN * 2, 256>>>();

    k_head<<<B, 512>>>(action, nsel, a_cw, a_cb,
                       a_w1, a_b1, a_w2, a_b2, a_w3, a_b3,
                       (float*)d_out);
}

// round 17
// speedup vs baseline: 1.2419x; 1.2419x over previous
#include <cuda_runtime.h>
#include <math.h>

#define LRELU(v) ((v) >= 0.0f ? (v) : 0.01f * (v))

constexpr int B  = 64;
constexpr int C0 = 3;
constexpr int NN = 500;
constexpr int T  = 50;
constexpr int R  = 4;
constexpr int P  = 500;
constexpr int H  = 128;
constexpr int CM = 3;
constexpr int CF = 20;
constexpr int F  = 43;         // 2*CF + C0
constexpr int E_MAX = 16000;
constexpr int BF = B * F;      // 2752
constexpr int BF4 = BF / 4;    // 688

// ---------------- scratch (static device globals; no allocation) ----------------
__device__ float d_x[B * NN * F];            // temporal features, [b][n][f]
__device__ float d_h2[NN * R * B * F];       // transformed feats [src][r][b][f]
__device__ float d_g[B * NN * F];            // gnn root-out (read-only in agg)
__device__ float d_dot[B * NN];              // per-(b,node) logits contribution
__device__ int   d_csr_off[NN + 1];
__device__ int   d_csr_se[E_MAX];            // packed (src<<2)|type, grouped by dst
__device__ float d_invdeg[R * NN];
__device__ float d_gsc[F], d_gsh[F];         // gnn BN scale/shift
__device__ float c_acw[88];                  // a_cw[0..86], a_cb at [87]

__global__ void k_prep(const float* __restrict__ a_cw, const float* __restrict__ a_cb)
{
    int tid = threadIdx.x;
    if (tid < 87) c_acw[tid] = a_cw[tid];
    if (tid == 87) c_acw[87] = a_cb[0];
}

// =================================================================================
// Kernel 1: fused temporal features (2048 blocks) + CSR graph build (block 0).
// (Exact version measured at 58us in R12.)
// =================================================================================
constexpr int NT  = 16;
constexpr int KS  = CM * 48;   // 144
constexpr int KSP = 145;
constexpr int KM  = CM * 30;   // 90
constexpr int KMP = 91;

struct TemporalSmem {
    float sw2s[CF * KSP];
    float sw2m[CF * KMP];
    float sw1s[CM * C0 * 3];
    float sw1m[CM * C0 * 21];
    float sobs[C0][NT][T];
    float sacts[NT * KSP];
    float sactm[NT * KMP];
    float a1s[CM], c1s[CM], a1m[CM], c1m[CM];
    float a2s[CF], c2s[CF], a2m[CF], c2m[CF];
};
struct GraphSmem {
    int cnt_all[NN];
    int cnt_rt[R * NN];
    int off[NN + 1];
    int cur[NN];
};
union SmemU {
    TemporalSmem t;
    GraphSmem g;
};

__global__ __launch_bounds__(256) void k_temporal(
    const float* __restrict__ obs,
    const int* __restrict__ ei, const int* __restrict__ et, int E,
    const float* __restrict__ gbn,
    const float* __restrict__ sc1_w, const float* __restrict__ sc1_b, const float* __restrict__ sbn1,
    const float* __restrict__ sc2_w, const float* __restrict__ sc2_b, const float* __restrict__ sbn2,
    const float* __restrict__ mc1_w, const float* __restrict__ mc1_b, const float* __restrict__ mbn1,
    const float* __restrict__ mc2_w, const float* __restrict__ mc2_b, const float* __restrict__ mbn2)
{
    __shared__ SmemU sm;
    const int tid = threadIdx.x;

    // ---------------- block 0: CSR graph build (hidden under conv blocks) ----
    if (blockIdx.x == 0) {
        for (int i = tid; i < NN; i += 256) sm.g.cnt_all[i] = 0;
        for (int i = tid; i < R * NN; i += 256) sm.g.cnt_rt[i] = 0;
        __syncthreads();
        for (int e = tid; e < E; e += 256) {
            int d = ei[E + e];
            atomicAdd(&sm.g.cnt_all[d], 1);
            atomicAdd(&sm.g.cnt_rt[et[e] * NN + d], 1);
        }
        __syncthreads();
        if (tid < 32) {
            int carry = 0;
            for (int base = 0; base < NN; base += 32) {
                int idx = base + tid;
                int c = (idx < NN) ? sm.g.cnt_all[idx] : 0;
                int v = c;
                #pragma unroll
                for (int o = 1; o < 32; o <<= 1) {
                    int t2 = __shfl_up_sync(0xffffffffu, v, o);
                    if (tid >= o) v += t2;
                }
                if (idx < NN) sm.g.off[idx] = carry + v - c;
                carry += __shfl_sync(0xffffffffu, v, 31);
            }
            if (tid == 0) sm.g.off[NN] = carry;
        }
        __syncthreads();
        for (int i = tid; i <= NN; i += 256) d_csr_off[i] = sm.g.off[i];
        for (int i = tid; i < NN; i += 256) sm.g.cur[i] = sm.g.off[i];
        for (int i = tid; i < R * NN; i += 256) {
            int c = sm.g.cnt_rt[i];
            d_invdeg[i] = 1.0f / (float)(c > 1 ? c : 1);
        }
        if (tid < F) {
            float g = gbn[tid], be = gbn[F + tid], mu = gbn[2 * F + tid], vv = gbn[3 * F + tid];
            float sc = g * rsqrtf(vv + 1e-5f);
            d_gsc[tid] = sc;
            d_gsh[tid] = be - mu * sc;
        }
        __syncthreads();
        for (int e = tid; e < E; e += 256) {
            int d = ei[E + e];
            int p = atomicAdd(&sm.g.cur[d], 1);
            d_csr_se[p] = (ei[e] << 2) | et[e];
        }
        return;
    }

    // ---------------- temporal path ----------------
    const int bid = blockIdx.x - 1;
    const int b  = bid >> 5;
    const int n0 = (bid & 31) * NT;

    for (int i = tid; i < CF * KS; i += 256) sm.t.sw2s[(i / KS) * KSP + (i % KS)] = sc2_w[i];
    for (int i = tid; i < CF * KM; i += 256) sm.t.sw2m[(i / KM) * KMP + (i % KM)] = mc2_w[i];
    for (int i = tid; i < CM * C0 * 3;  i += 256) sm.t.sw1s[i] = sc1_w[i];
    for (int i = tid; i < CM * C0 * 21; i += 256) sm.t.sw1m[i] = mc1_w[i];

    if (tid < CM) {
        float g = sbn1[tid], be = sbn1[3 + tid], mu = sbn1[6 + tid], vv = sbn1[9 + tid];
        float sc = g * rsqrtf(vv + 1e-5f);
        sm.t.a1s[tid] = sc; sm.t.c1s[tid] = (be - mu * sc) + sc1_b[tid] * sc;
        g = mbn1[tid]; be = mbn1[3 + tid]; mu = mbn1[6 + tid]; vv = mbn1[9 + tid];
        sc = g * rsqrtf(vv + 1e-5f);
        sm.t.a1m[tid] = sc; sm.t.c1m[tid] = (be - mu * sc) + mc1_b[tid] * sc;
    }
    if (tid < CF) {
        float g = sbn2[tid], be = sbn2[20 + tid], mu = sbn2[40 + tid], vv = sbn2[60 + tid];
        float sc = g * rsqrtf(vv + 1e-5f);
        sm.t.a2s[tid] = sc; sm.t.c2s[tid] = (be - mu * sc) + sc2_b[tid] * sc;
        g = mbn2[tid]; be = mbn2[20 + tid]; mu = mbn2[40 + tid]; vv = mbn2[60 + tid];
        sc = g * rsqrtf(vv + 1e-5f);
        sm.t.a2m[tid] = sc; sm.t.c2m[tid] = (be - mu * sc) + mc2_b[tid] * sc;
    }

    for (int i = tid; i < C0 * NT * T; i += 256) {
        int c = i / (NT * T);
        int rem = i % (NT * T);
        int ni = rem / T, t = rem % T;
        int n = n0 + ni;
        sm.t.sobs[c][ni][t] = (n < NN) ? obs[((b * C0 + c) * NN + n) * T + t] : 0.0f;
    }
    __syncthreads();

    // conv1 s-branch: 192 tasks (ni, c, 12-wide j block), register sliding window
    if (tid < 192) {
        int ni = tid / 12;
        int rem = tid % 12;
        int c = rem / 4, jb = rem % 4;
        int j0 = jb * 12;
        float acc[12];
        #pragma unroll
        for (int j = 0; j < 12; j++) acc[j] = 0.0f;
        #pragma unroll
        for (int ci = 0; ci < C0; ci++) {
            float win[14];
            #pragma unroll
            for (int t2 = 0; t2 < 14; t2++) win[t2] = sm.t.sobs[ci][ni][j0 + t2];
            #pragma unroll
            for (int k = 0; k < 3; k++) {
                float wv = sm.t.sw1s[c * 9 + ci * 3 + k];
                #pragma unroll
                for (int j = 0; j < 12; j++) acc[j] += win[j + k] * wv;
            }
        }
        float aa = sm.t.a1s[c], cc = sm.t.c1s[c];
        #pragma unroll
        for (int j = 0; j < 12; j++) {
            float v = acc[j] * aa + cc;
            sm.t.sacts[ni * KSP + c * 48 + j0 + j] = LRELU(v);
        }
    }
    // conv1 m-branch: 144 tasks (ni, c, 10-wide j block)
    if (tid < 144) {
        int ni = tid / 9;
        int rem = tid % 9;
        int c = rem / 3, jb = rem % 3;
        int j0 = jb * 10;
        float acc[10];
        #pragma unroll
        for (int j = 0; j < 10; j++) acc[j] = 0.0f;
        #pragma unroll
        for (int ci = 0; ci < C0; ci++) {
            float win[30];
            #pragma unroll
            for (int t2 = 0; t2 < 30; t2++) win[t2] = sm.t.sobs[ci][ni][j0 + t2];
            #pragma unroll
            for (int k = 0; k < 21; k++) {
                float wv = sm.t.sw1m[c * 63 + ci * 21 + k];
                #pragma unroll
                for (int j = 0; j < 10; j++) acc[j] += win[j + k] * wv;
            }
        }
        float aa = sm.t.a1m[c], cc = sm.t.c1m[c];
        #pragma unroll
        for (int j = 0; j < 10; j++) {
            float v = acc[j] * aa + cc;
            sm.t.sactm[ni * KMP + c * 30 + j0 + j] = LRELU(v);
        }
    }
    __syncthreads();

    // conv2: 2ni x 2cf register tiles, l-branch tasks 160..207
    if (tid < 80) {
        int nip = tid / 10, cfp = tid % 10;
        int ni0 = nip * 2, cf0 = cfp * 2;
        const float* a0 = &sm.t.sacts[ni0 * KSP];
        const float* a1 = &sm.t.sacts[(ni0 + 1) * KSP];
        const float* w0 = &sm.t.sw2s[cf0 * KSP];
        const float* w1 = &sm.t.sw2s[(cf0 + 1) * KSP];
        float acc00 = 0.f, acc01 = 0.f, acc10 = 0.f, acc11 = 0.f;
        #pragma unroll 8
        for (int k = 0; k < KS; k++) {
            float av0 = a0[k], av1 = a1[k];
            float wv0 = w0[k], wv1 = w1[k];
            acc00 += av0 * wv0; acc01 += av0 * wv1;
            acc10 += av1 * wv0; acc11 += av1 * wv1;
        }
        #pragma unroll
        for (int di = 0; di < 2; di++) {
            int n = n0 + ni0 + di;
            if (n >= NN) continue;
            float va = (di == 0) ? acc00 : acc10;
            float vb = (di == 0) ? acc01 : acc11;
            va = va * sm.t.a2s[cf0] + sm.t.c2s[cf0];
            vb = vb * sm.t.a2s[cf0 + 1] + sm.t.c2s[cf0 + 1];
            d_x[(size_t)(b * NN + n) * F + cf0]     = LRELU(va);
            d_x[(size_t)(b * NN + n) * F + cf0 + 1] = LRELU(vb);
        }
    } else if (tid < 160) {
        int t2 = tid - 80;
        int nip = t2 / 10, cfp = t2 % 10;
        int ni0 = nip * 2, cf0 = cfp * 2;
        const float* a0 = &sm.t.sactm[ni0 * KMP];
        const float* a1 = &sm.t.sactm[(ni0 + 1) * KMP];
        const float* w0 = &sm.t.sw2m[cf0 * KMP];
        const float* w1 = &sm.t.sw2m[(cf0 + 1) * KMP];
        float acc00 = 0.f, acc01 = 0.f, acc10 = 0.f, acc11 = 0.f;
        #pragma unroll 6
        for (int k = 0; k < KM; k++) {
            float av0 = a0[k], av1 = a1[k];
            float wv0 = w0[k], wv1 = w1[k];
            acc00 += av0 * wv0; acc01 += av0 * wv1;
            acc10 += av1 * wv0; acc11 += av1 * wv1;
        }
        #pragma unroll
        for (int di = 0; di < 2; di++) {
            int n = n0 + ni0 + di;
            if (n >= NN) continue;
            float va = (di == 0) ? acc00 : acc10;
            float vb = (di == 0) ? acc01 : acc11;
            va = va * sm.t.a2m[cf0] + sm.t.c2m[cf0];
            vb = vb * sm.t.a2m[cf0 + 1] + sm.t.c2m[cf0 + 1];
            d_x[(size_t)(b * NN + n) * F + 20 + cf0]     = LRELU(va);
            d_x[(size_t)(b * NN + n) * F + 20 + cf0 + 1] = LRELU(vb);
        }
    } else if (tid < 208) {
        int i2 = tid - 160;
        int ni = i2 / C0, c = i2 % C0;
        int n = n0 + ni;
        float mx = sm.t.sobs[c][ni][0];
        #pragma unroll
        for (int t = 1; t < T; t++) mx = fmaxf(mx, sm.t.sobs[c][ni][t]);
        if (n < NN) d_x[(size_t)(b * NN + n) * F + 40 + c] = LRELU(mx);
    }
}

// =================================================================================
// Kernel 2: y = x @ [gw_root | gw_rel0..3]  (32000 x 43) @ (43 x 215)
// =================================================================================
__global__ __launch_bounds__(256) void k_gnn_mm(
    const float* __restrict__ gw_root, const float* __restrict__ gw_rel,
    const float* __restrict__ g_b)
{
    __shared__ float xs[F * 65];
    __shared__ float sW[F * 216];
    __shared__ float sgb[F];

    const int tid = threadIdx.x;
    const int r0 = blockIdx.x * 64;

    for (int i = tid; i < 64 * F; i += 256) {
        int rr = i / F, k = i % F;
        xs[k * 65 + rr] = d_x[(size_t)(r0 + rr) * F + k];
    }
    for (int i = tid; i < F * 215; i += 256) {
        int k = i / 215, col = i % 215;
        float v;
        if (col < F) v = gw_root[k * F + col];
        else {
            int cc = col - F;
            int rr = cc / F, g = cc % F;
            v = gw_rel[(rr * F + k) * F + g];
        }
        sW[k * 216 + col] = v;
    }
    if (tid < F) sgb[tid] = g_b[tid];
    __syncthreads();

    if (tid < 216) {
        int rg = tid % 8;
        int cc = tid / 8;
        int col0 = cc * 8;
        float acc[8][8];
        #pragma unroll
        for (int i = 0; i < 8; i++)
            #pragma unroll
            for (int j = 0; j < 8; j++) acc[i][j] = 0.0f;

        for (int k = 0; k < F; k++) {
            float xv[8], wv[8];
            #pragma unroll
            for (int i = 0; i < 8; i++) xv[i] = xs[k * 65 + rg * 8 + i];
            #pragma unroll
            for (int j = 0; j < 8; j++) wv[j] = sW[k * 216 + col0 + j];
            #pragma unroll
            for (int i = 0; i < 8; i++)
                #pragma unroll
                for (int j = 0; j < 8; j++) acc[i][j] += xv[i] * wv[j];
        }
        #pragma unroll
        for (int i = 0; i < 8; i++) {
            int row = r0 + rg * 8 + i;
            int bb = row / NN, n = row % NN;
            #pragma unroll
            for (int j = 0; j < 8; j++) {
                int col = col0 + j;
                if (col < 215) {
                    if (col < F) {
                        d_g[(size_t)row * F + col] = acc[i][j] + sgb[col];
                    } else {
                        int cc2 = col - F;
                        int rr = cc2 / F, g = cc2 % F;
                        d_h2[(size_t)((n * R + rr) * B + bb) * F + g] = acc[i][j];
                    }
                }
            }
        }
    }
}

// =================================================================================
// Kernel 3: aggregation + fused logits dot. Two blocks per node (batch halves,
// split cleanly at bb=32: 344*4 = 1376 = 32*43). Final g never hits DRAM;
// per-(b,n) logits contribution reduced via shared atomics -> d_dot.
// =================================================================================
__global__ __launch_bounds__(256) void k_agg()
{
    constexpr int CH = 128;
    constexpr int HALF4 = BF4 / 2;        // 344 float4 per half
    __shared__ int   sbase[CH];
    __shared__ float sws[CH];
    __shared__ float swx[F], swg[F];
    __shared__ float sdot[32];

    const int tid = threadIdx.x;
    const int n = blockIdx.x >> 1;
    const int s = blockIdx.x & 1;
    const int j4base = s * HALF4;
    const int off0 = d_csr_off[n];
    const int cnt  = d_csr_off[n + 1] - off0;

    if (tid < F) { swx[tid] = c_acw[1 + tid]; swg[tid] = c_acw[44 + tid]; }
    if (tid < 32) sdot[tid] = 0.0f;
    __syncthreads();

    float4 acc0 = make_float4(0.f, 0.f, 0.f, 0.f);
    float4 acc1 = make_float4(0.f, 0.f, 0.f, 0.f);

    for (int base = 0; base < cnt; base += CH) {
        int lim = min(CH, cnt - base);
        if (tid < lim) {
            int se = d_csr_se[off0 + base + tid];
            int src = se >> 2, r = se & 3;
            sbase[tid] = (src * R + r) * BF;
            sws[tid]   = d_invdeg[r * NN + n];
        }
        __syncthreads();
        for (int i = 0; i < lim; i++) {
            const float4* hp = (const float4*)(d_h2 + sbase[i]) + j4base;
            const float w = sws[i];
            float4 v0 = hp[tid];
            acc0.x += v0.x * w; acc0.y += v0.y * w; acc0.z += v0.z * w; acc0.w += v0.w * w;
            if (tid < HALF4 - 256) {
                float4 v1 = hp[tid + 256];
                acc1.x += v1.x * w; acc1.y += v1.y * w; acc1.z += v1.z * w; acc1.w += v1.w * w;
            }
        }
        __syncthreads();
    }

    // epilogue: finish g, fold into logits dot (no d_g store)
    float accs[8] = {acc0.x, acc0.y, acc0.z, acc0.w,
                     acc1.x, acc1.y, acc1.z, acc1.w};
    #pragma unroll
    for (int u = 0; u < 2; u++) {
        int j4 = j4base + tid + 256 * u;
        if (tid + 256 * u < HALF4) {
            float run = 0.0f;
            int runbb = (j4 * 4) / F;
            #pragma unroll
            for (int c = 0; c < 4; c++) {
                int j = j4 * 4 + c;
                int bb = j / F, f = j - bb * F;
                size_t idx = (size_t)(bb * NN + n) * F + f;
                float v = d_g[idx] + accs[u * 4 + c];
                v = v * d_gsc[f] + d_gsh[f];
                v = LRELU(v);
                float con = swg[f] * v + swx[f] * d_x[idx];
                if (bb != runbb) {
                    atomicAdd(&sdot[runbb - s * 32], run);
                    run = 0.0f;
                    runbb = bb;
                }
                run += con;
            }
            atomicAdd(&sdot[runbb - s * 32], run);
        }
    }
    __syncthreads();
    if (tid < 32)
        d_dot[(size_t)(s * 32 + tid) * NN + n] = sdot[tid];
}

// =================================================================================
// Kernel 4: per-batch MLP + softmax; logits assembled from d_dot. grid=64 x 512.
// =================================================================================
__global__ __launch_bounds__(512) void k_mlp(
    const float* __restrict__ action, const int* __restrict__ nsel,
    const float* __restrict__ w1, const float* __restrict__ b1,
    const float* __restrict__ w2, const float* __restrict__ b2,
    const float* __restrict__ w3, const float* __restrict__ b3,
    float* __restrict__ out)
{
    __shared__ float so[P + 1];
    __shared__ float sh1[H];
    __shared__ float sh2[H];
    __shared__ float sz[P + 1];
    __shared__ float sred[512];

    const int tid = threadIdx.x;
    const int b = blockIdx.x;
    const int quarter = tid >> 7;
    const int o = tid & 127;

    if (tid < P) {
        int node = nsel[tid];
        so[tid + 1] = d_dot[(size_t)b * NN + node]
                    + c_acw[87] + c_acw[0] * action[b * (P + 1) + tid + 1];
    }
    if (tid == 0) so[0] = 0.0f;
    __syncthreads();

    {
        const int k0 = quarter * 126;
        const int k1 = min(501, k0 + 126);
        float acc = (quarter == 0) ? b1[o] : 0.0f;
        #pragma unroll 6
        for (int k = k0; k < k1; k++) acc += so[k] * w1[k * H + o];
        sred[tid] = acc;
        __syncthreads();
        if (tid < H)
            sh1[tid] = fmaxf(sred[tid] + sred[tid + 128] + sred[tid + 256] + sred[tid + 384], 0.0f);
        __syncthreads();
    }

    {
        const int k0 = quarter * 32;
        float acc = (quarter == 0) ? b2[o] : 0.0f;
        #pragma unroll 8
        for (int k = k0; k < k0 + 32; k++) acc += sh1[k] * w2[k * H + o];
        sred[tid] = acc;
        __syncthreads();
        if (tid < H)
            sh2[tid] = fmaxf(sred[tid] + sred[tid + 128] + sred[tid + 256] + sred[tid + 384], 0.0f);
        __syncthreads();
    }

    if (tid < P + 1) {
        float acc = b3[tid];
        #pragma unroll 16
        for (int k = 0; k < H; k++) acc += sh2[k] * w3[k * (P + 1) + tid];
        sz[tid] = acc;
    }
    __syncthreads();

    float lm = (tid < P + 1) ? sz[tid] : -1e30f;
    sred[tid] = lm;
    __syncthreads();
    for (int s = 256; s > 0; s >>= 1) {
        if (tid < s) sred[tid] = fmaxf(sred[tid], sred[tid + s]);
        __syncthreads();
    }
    float mx = sred[0];
    __syncthreads();

    float ls = 0.0f;
    if (tid < P + 1) {
        float e = expf(sz[tid] - mx);
        sz[tid] = e;
        ls = e;
    }
    sred[tid] = ls;
    __syncthreads();
    for (int s = 256; s > 0; s >>= 1) {
        if (tid < s) sred[tid] += sred[tid + s];
        __syncthreads();
    }
    float inv = 1.0f / sred[0];
    if (tid < P + 1)
        out[b * (P + 1) + tid] = sz[tid] * inv;
}

// =================================================================================
extern "C" void kernel_launch(void* const* d_in, const int* in_sizes, int n_in,
                              void* d_out, int out_size)
{
    const float* obs    = (const float*)d_in[0];
    const float* action = (const float*)d_in[1];
    const int*   ei     = (const int*)d_in[2];
    const int*   et     = (const int*)d_in[3];
    const int*   nsel   = (const int*)d_in[4];
    const float* sc1_w  = (const float*)d_in[5];
    const float* sc1_b  = (const float*)d_in[6];
    const float* sbn1   = (const float*)d_in[7];
    const float* sc2_w  = (const float*)d_in[8];
    const float* sc2_b  = (const float*)d_in[9];
    const float* sbn2   = (const float*)d_in[10];
    const float* mc1_w  = (const float*)d_in[11];
    const float* mc1_b  = (const float*)d_in[12];
    const float* mbn1   = (const float*)d_in[13];
    const float* mc2_w  = (const float*)d_in[14];
    const float* mc2_b  = (const float*)d_in[15];
    const float* mbn2   = (const float*)d_in[16];
    const float* gw_root= (const float*)d_in[17];
    const float* gw_rel = (const float*)d_in[18];
    const float* g_b    = (const float*)d_in[19];
    const float* gbn    = (const float*)d_in[20];
    const float* a_cw   = (const float*)d_in[21];
    const float* a_cb   = (const float*)d_in[22];
    const float* a_w1   = (const float*)d_in[23];
    const float* a_b1   = (const float*)d_in[24];
    const float* a_w2   = (const float*)d_in[25];
    const float* a_b2   = (const float*)d_in[26];
    const float* a_w3   = (const float*)d_in[27];
    const float* a_b3   = (const float*)d_in[28];

    const int E = in_sizes[3];

    k_prep<<<1, 96>>>(a_cw, a_cb);

    k_temporal<<<B * 32 + 1, 256>>>(obs, ei, et, E, gbn,
        sc1_w, sc1_b, sbn1, sc2_w, sc2_b, sbn2,
        mc1_w, mc1_b, mbn1, mc2_w, mc2_b, mbn2);

    k_gnn_mm<<<(B * NN) / 64, 256>>>(gw_root, gw_rel, g_b);

    k_agg<<<NN * 2, 256>>>();

    k_mlp<<<B, 512>>>(action, nsel,
                      a_w1, a_b1, a_w2, a_b2, a_w3, a_b3,
                      (float*)d_out);
}